// round 16
// baseline (speedup 1.0000x reference)
#include <cuda_runtime.h>
#include <math.h>

#define BATCH  64
#define LSUB   512
#define SWORDS 512
#define HID    768
#define NC     9
#define NWORDS (BATCH * SWORDS)
#define MGRID  296          // 2 blocks/SM, one wave
#define PPB    4            // warp-pairs per block

typedef unsigned long long u64;

__device__ int   g_ls[NWORDS];        // (start<<2)|len
__device__ int   g_widx[NWORDS];      // compacted valid word ids
__device__ int   g_total;
__device__ int   g_alloc;
__device__ int   g_done0;
__device__ float g_loss;
__device__ int   g_cnt;
__device__ int   g_done;

__device__ __forceinline__ u64 fma2(u64 a, u64 b, u64 c) {
    u64 d; asm("fma.rn.f32x2 %0,%1,%2,%3;" : "=l"(d) : "l"(a), "l"(b), "l"(c)); return d;
}
__device__ __forceinline__ u64 add2(u64 a, u64 b) {
    u64 d; asm("add.rn.f32x2 %0,%1,%2;" : "=l"(d) : "l"(a), "l"(b)); return d;
}
__device__ __forceinline__ float upk_sum(u64 v) {
    float lo, hi; asm("mov.b64 {%0,%1},%2;" : "=f"(lo), "=f"(hi) : "l"(v)); return lo + hi;
}

// ---------------------------------------------------------------------------
// Setup (R11, proven): scan -> g_ls, compaction -> g_widx/g_total,
// default preds = argmax(bias), self-cleaning counters.
// ---------------------------------------------------------------------------
__global__ void __launch_bounds__(256) setup_kernel(
    const int* __restrict__ ids_lens, const float* __restrict__ W,
    const float* __restrict__ bias, float* __restrict__ out)
{
    __shared__ int s_comb[8];
    __shared__ int s_off;
    const int b = blockIdx.x, tid = threadIdx.x;
    const int lane = tid & 31, warp = tid >> 5;

    int2 lp = ((const int2*)(ids_lens + b * SWORDS))[tid];
    int f0 = (lp.x > 0), f1 = (lp.y > 0);
    int comb = ((lp.x + lp.y) << 16) | (f0 + f1);
    int inc = comb;
#pragma unroll
    for (int off = 1; off < 32; off <<= 1) {
        int n = __shfl_up_sync(0xffffffffu, inc, off);
        if (lane >= off) inc += n;
    }
    int lane_ex = inc - comb;
    if (lane == 31) s_comb[warp] = inc;
    __syncthreads();
    int wbase = 0;
#pragma unroll
    for (int i = 0; i < 8; i++) if (i < warp) wbase += s_comb[i];
    int ex = wbase + lane_ex;
    int st0 = ex >> 16;
    int vx  = ex & 0xffff;

    const int base = b * SWORDS + 2 * tid;
    g_ls[base]     = (st0 << 2) | lp.x;
    g_ls[base + 1] = ((st0 + lp.x) << 2) | lp.y;

    if (tid == 0) {
        int t = 0;
#pragma unroll
        for (int i = 0; i < 8; i++) t += s_comb[i];
        s_off = atomicAdd(&g_alloc, t & 0xffff);
    }
    __syncthreads();
    int pos = s_off + vx;
    if (f0) g_widx[pos]      = base;
    if (f1) g_widx[pos + f0] = base + 1;

    {
        float m = -1e30f; int am = 0;
#pragma unroll
        for (int c = 0; c < NC; c++) { float v = bias[c]; if (v > m) { m = v; am = c; } }
        out[1 + base] = (float)am; out[1 + base + 1] = (float)am;
    }
    if (tid == 0) {
        __threadfence();
        int old = atomicAdd(&g_done0, 1);
        if (old == BATCH - 1) {
            g_total = atomicAdd(&g_alloc, 0);
            atomicExch(&g_alloc, 0);
            atomicExch(&g_done0, 0);
        }
    }
}

// ---------------------------------------------------------------------------
// Main: 296 blocks x 256 threads. 2 warps per word-pair (split-K halves of H).
// Within a warp, lanes 0-15 own word0, lanes 16-31 own word1 (9 u64 accs).
// Software-pipelined: iteration i+1's 18-load batch is issued before
// computing iteration i, so LDGs are in flight ~continuously.
// ---------------------------------------------------------------------------
__global__ void __launch_bounds__(256, 2) main_kernel(
    const float* __restrict__ x,        // [B, L, H]
    const float* __restrict__ W,        // [H, C]
    const float* __restrict__ bias,     // [C]
    const int*   __restrict__ label_ids,
    float*       __restrict__ out)      // out[0]=loss, out[1..]=pred
{
    __shared__ float Ws[NC * HID];      // Ws[c*HID + h]
    __shared__ float sb[NC];
    __shared__ float s_part[PPB][2][2][NC];  // [pair][parity][word][class]
    __shared__ float s_loss;
    __shared__ int   s_cnt;

    const int tid  = threadIdx.x;
    const int lane = tid & 31;
    const int warp = tid >> 5;
    const int pr   = warp >> 1;         // warp-pair 0..3
    const int half = warp & 1;          // K-half
    const int l16  = lane & 15;
    const int hi16 = lane >> 4;         // 0 = word0, 1 = word1

    for (int j = tid; j < NC * HID; j += 256) {
        int c = j / HID;
        int h = j - c * HID;
        Ws[j] = W[h * NC + c];
    }
    if (tid < NC) sb[tid] = bias[tid];
    if (tid == 0) { s_loss = 0.0f; s_cnt = 0; }
    __syncthreads();

    const int total  = g_total;
    const int npairs = (total + 1) >> 1;
    const int nstride = MGRID * PPB;
    const int2* widx2 = (const int2*)g_widx;

    float lloss = 0.0f;
    int   lcnt  = 0;

    const ulonglong2 z2 = make_ulonglong2(0ull, 0ull);
    const int RS = HID / 4;             // 192 ulonglong2 per row
    const int cb = half * 96 + l16;     // this lane's chunk base within a row
    const int bid = pr + 1;             // named barrier 1..4

    // ---- per-lane meta fetch for pair p ----
    auto fetch = [&](int p, int2& wp, int& mylen, const ulonglong2*& mybase, bool& a1) {
        wp = make_int2(0, 0); mylen = 0; a1 = false;
        mybase = (const ulonglong2*)x;
        if (p < npairs) {
            wp = widx2[p];
            a1 = (2 * p + 1 < total);
            int w  = hi16 ? wp.y : wp.x;
            int ls = (hi16 && !a1) ? 0 : g_ls[w];
            mylen = ls & 3;
            mybase = (const ulonglong2*)(x + ((size_t)((w >> 9) * LSUB + (ls >> 2))) * HID);
        }
    };
    // ---- batched 18-load (predicated) ----
    auto loadb = [&](ulonglong2* r, const ulonglong2* base, int len) {
#pragma unroll
        for (int g = 0; g < 6; g++) {
            int idx = cb + g * 16;
            r[g*3+0] = (len > 0) ? base[idx]          : z2;
            r[g*3+1] = (len > 1) ? base[idx + RS]     : z2;
            r[g*3+2] = (len > 2) ? base[idx + 2*RS]   : z2;
        }
    };

    int p = blockIdx.x * PPB + pr;
    int2 wp;  int mylen;  const ulonglong2* mybase;  bool act1;
    fetch(p, wp, mylen, mybase, act1);
    ulonglong2 rA[18];
    if (p < npairs) loadb(rA, mybase, mylen);

    int it = 0;
#pragma unroll 2
    while (p < npairs) {
        // ---- prefetch next pair's meta + issue its load batch ----
        int pn = p + nstride;
        int2 wpn;  int mylenN;  const ulonglong2* mybaseN;  bool act1N;
        fetch(pn, wpn, mylenN, mybaseN, act1N);
        ulonglong2 rB[18];
        loadb(rB, mybaseN, (pn < npairs) ? mylenN : 0);

        // ---- compute current pair from rA ----
        u64 acc[NC];
#pragma unroll
        for (int c = 0; c < NC; c++) acc[c] = 0ull;

#pragma unroll
        for (int g = 0; g < 6; g++) {
            u64 vl = add2(rA[g*3+0].x, add2(rA[g*3+1].x, rA[g*3+2].x));
            u64 vh = add2(rA[g*3+0].y, add2(rA[g*3+1].y, rA[g*3+2].y));
            int hb = half * 384 + g * 64 + l16 * 4;
#pragma unroll
            for (int c = 0; c < NC; c++) {
                ulonglong2 wc = *(const ulonglong2*)&Ws[c * HID + hb];
                acc[c] = fma2(vl, wc.x, acc[c]);
                acc[c] = fma2(vh, wc.y, acc[c]);
            }
        }

        // ---- reduce within each 16-lane half (word0 -> lane0, word1 -> lane16)
        float v[NC];
#pragma unroll
        for (int c = 0; c < NC; c++) {
            v[c] = upk_sum(acc[c]);
#pragma unroll
            for (int off = 8; off; off >>= 1)
                v[c] += __shfl_xor_sync(0xffffffffu, v[c], off);
        }

        // ---- cross-warp (split-K) combine ----
        int par = it & 1;
        if (half == 1 && l16 == 0) {
#pragma unroll
            for (int c = 0; c < NC; c++) s_part[pr][par][hi16][c] = v[c];
        }
        asm volatile("bar.sync %0, 64;" :: "r"(bid) : "memory");

        if (half == 0 && l16 == 0 && (hi16 == 0 || act1)) {
            int   w   = hi16 ? wp.y : wp.x;
            const float* po = s_part[pr][par][hi16];
            float inv = 1.0f / (float)mylen;
            float lg[NC];
            float m = -1e30f; int am = 0;
#pragma unroll
            for (int c = 0; c < NC; c++) {
                lg[c] = fmaf(v[c] + po[c], inv, sb[c]);
                if (lg[c] > m) { m = lg[c]; am = c; }
            }
            out[1 + w] = (float)am;
            float sum = 0.0f;
#pragma unroll
            for (int c = 0; c < NC; c++) sum += __expf(lg[c] - m);
            int lab = label_ids[w];
            lab = lab < 0 ? 0 : (lab > NC - 1 ? NC - 1 : lab);
            lloss += -(lg[lab] - m - __logf(sum));
            lcnt  += 1;
        }

        // ---- rotate pipeline ----
        p = pn; wp = wpn; mylen = mylenN; mybase = mybaseN; act1 = act1N;
#pragma unroll
        for (int i = 0; i < 18; i++) rA[i] = rB[i];
        it++;
    }

    // word1 losses live on lane 0 too (hi16 check used lane's own l16==0);
    // merge lane16-side partials: only lanes with l16==0 accumulated.
    lloss += __shfl_xor_sync(0xffffffffu, lloss, 16);
    lcnt  += __shfl_xor_sync(0xffffffffu, lcnt,  16);
    if (lane == 0 && lcnt > 0) {
        atomicAdd(&s_loss, lloss);
        atomicAdd(&s_cnt, lcnt);
    }
    __syncthreads();

    if (tid == 0) {
        if (s_cnt > 0) {
            atomicAdd(&g_loss, s_loss);
            atomicAdd(&g_cnt, s_cnt);
        }
        __threadfence();
        int old = atomicAdd(&g_done, 1);
        if (old == MGRID - 1) {
            float lv = atomicAdd(&g_loss, 0.0f);
            int   cv = atomicAdd(&g_cnt, 0);
            out[0] = lv / fmaxf((float)cv, 1.0f);
            g_loss = 0.0f; g_cnt = 0;
            atomicExch(&g_done, 0);
        }
    }
}

extern "C" void kernel_launch(void* const* d_in, const int* in_sizes, int n_in,
                              void* d_out, int out_size) {
    const float* bert_out  = (const float*)d_in[0];
    const float* W         = (const float*)d_in[1];
    const float* b         = (const float*)d_in[2];
    const int*   ids_lens  = (const int*)d_in[4];
    const int*   label_ids = (const int*)d_in[5];
    float* out = (float*)d_out;

    setup_kernel<<<BATCH, 256>>>(ids_lens, W, b, out);
    main_kernel<<<MGRID, 256>>>(bert_out, W, b, label_ids, out);
}